// round 14
// baseline (speedup 1.0000x reference)
#include <cuda_runtime.h>

#define ACC 23
#define UNROLL 4
#define TPB 256

struct Consts {
    int       nm_x, nm_id;
    int       sr_x, sr_id;
    int       sl_x, sl_id;
    int       left_x, left_id;
    int       kx32, kid32;   // (1 << (sr-1)), 0 if sr==0 (fits int32 when sr<=31)
    long long kx, kid;       // 64-bit versions for generic path
    int       fast;          // both streams eligible for 32-bit fast path
    float     scale;
};

// Exact replication of the reference's fp64 scale decomposition.
__device__ __forceinline__ void compute_consts(const float* __restrict__ pre_sf,
                                               const float* __restrict__ id_sf,
                                               const float* __restrict__ x_min,
                                               const float* __restrict__ x_max,
                                               Consts* c) {
    float scale = fmaxf(fabsf(x_min[0]), fabsf(x_max[0]));
    scale = fmaxf(scale, 1e-8f);
    scale = scale / 127.0f;
    double s64 = (double)scale;
    {
        double ns = (double)pre_sf[0] / s64;
        int e; double m = frexp(ns, &e);             // m in [0.5, 1)
        c->nm_x   = (int)llrint(m * 8388608.0);      // round-half-even == jnp.round
        c->sl_x   = max(e - ACC, 0);
        c->sr_x   = max(ACC - e, 0);
        c->left_x = (e - ACC) >= 0;
        c->kx32   = (c->sr_x > 0 && c->sr_x <= 31) ? (1 << (c->sr_x - 1)) : 0;
        c->kx     = (c->sr_x > 0) ? (1LL << (c->sr_x - 1)) : 0LL;
    }
    {
        double ns = (double)id_sf[0] / s64;
        int e; double m = frexp(ns, &e);
        c->nm_id   = (int)llrint(m * 8388608.0);
        c->sl_id   = max(e - ACC, 0);
        c->sr_id   = max(ACC - e, 0);
        c->left_id = (e - ACC) >= 0;
        c->kid32   = (c->sr_id > 0 && c->sr_id <= 31) ? (1 << (c->sr_id - 1)) : 0;
        c->kid     = (c->sr_id > 0) ? (1LL << (c->sr_id - 1)) : 0LL;
    }
    // Fast path: right-shift branch on both streams, sr in [15,31].
    // sr >= 15 guarantees |(xi*nm)>>sr| < 2^31 for |xi| < 2^22 (exact-int fp32
    // inputs from int32 accumulators), so 32-bit extraction is exact.
    c->fast = (!c->left_x && !c->left_id &&
               c->sr_x >= 15 && c->sr_x <= 31 &&
               c->sr_id >= 15 && c->sr_id <= 31);
    c->scale = scale;
}

// ---------------- generic bit-exact path (any consts) ----------------
__device__ __forceinline__ long long fpmul_gen(int xi, int nm, int sr, int sl,
                                               int left, long long k) {
    long long tmp = (long long)xi * (long long)nm;
    if (left) return tmp << sl;
    if (sr == 0) return tmp;
    return (tmp + (k - (long long)(tmp < 0))) >> sr;
}

__device__ __forceinline__ float quant_gen(float xv, float iv, const Consts& c) {
    int xi = (int)xv;
    int ii = (int)iv;
    long long rx = fpmul_gen(xi, c.nm_x,  c.sr_x,  c.sl_x,  c.left_x,  c.kx);
    long long ri = fpmul_gen(ii, c.nm_id, c.sr_id, c.sl_id, c.left_id, c.kid);
    long long s  = rx + ri;
    int q = (int)(s < -128 ? -128 : (s > 127 ? 127 : s));
    return (float)q * c.scale;
}

// ---------------- fast 32-bit path ----------------
// float -> int, exact for integer-valued v with |v| < 2^22
__device__ __forceinline__ int f2i_magic(float v) {
    float f = v + 12582912.0f;             // 2^23 + 2^22
    return __float_as_int(f) - 0x4B400000;
}
// int -> float, exact for q in [-2^22, 2^22)
__device__ __forceinline__ float i2f_magic(int q) {
    return __int_as_float(q + 0x4B400000) - 12582912.0f;
}

// round((xi*nm) / 2^sr) half-away-from-zero; nm > 0 so sign(tmp) == sign(xi).
__device__ __forceinline__ int fpmul_fast(int xi, int nm, int sr, int k) {
    unsigned b = (unsigned)xi >> 31;                       // 1 = negative
    long long tmp = (long long)xi * (long long)nm
                  + (long long)(unsigned)(k - (int)b);     // IMAD.WIDE w/ addend
    unsigned lo = (unsigned)tmp;
    unsigned hi = (unsigned)((unsigned long long)tmp >> 32);
    return (int)__funnelshift_r(lo, hi, sr);               // low 32 bits of >> sr
}

__device__ __forceinline__ float quant_fast(float xv, float iv, const Consts& c) {
    int xi = f2i_magic(xv);
    int ii = f2i_magic(iv);
    int rx = fpmul_fast(xi, c.nm_x,  c.sr_x,  c.kx32);
    int ri = fpmul_fast(ii, c.nm_id, c.sr_id, c.kid32);
    int s  = rx + ri;
    s = max(s, -128);
    s = min(s, 127);
    return i2f_magic(s) * c.scale;
}

__device__ __forceinline__ float4 quant4_fast(float4 xv, float4 iv, const Consts& c) {
    float4 ov;
    ov.x = quant_fast(xv.x, iv.x, c);
    ov.y = quant_fast(xv.y, iv.y, c);
    ov.z = quant_fast(xv.z, iv.z, c);
    ov.w = quant_fast(xv.w, iv.w, c);
    return ov;
}

__device__ __forceinline__ float4 quant4_gen(float4 xv, float4 iv, const Consts& c) {
    float4 ov;
    ov.x = quant_gen(xv.x, iv.x, c);
    ov.y = quant_gen(xv.y, iv.y, c);
    ov.z = quant_gen(xv.z, iv.z, c);
    ov.w = quant_gen(xv.w, iv.w, c);
    return ov;
}

__global__ void __launch_bounds__(TPB)
fused_quant_kernel(const float4* __restrict__ x,
                   const float4* __restrict__ idn,
                   float4* __restrict__ out,
                   const float* __restrict__ pre_sf,
                   const float* __restrict__ id_sf,
                   const float* __restrict__ x_min,
                   const float* __restrict__ x_max,
                   int n4, int n, int out_size, int full_sweeps) {
    __shared__ Consts sc;
    if (threadIdx.x == 0) {
        compute_consts(pre_sf, id_sf, x_min, x_max, &sc);
    }
    __syncthreads();
    const Consts c = sc;

    const int stride = gridDim.x * TPB * UNROLL;         // float4 per sweep
    int i = blockIdx.x * (TPB * UNROLL) + threadIdx.x;

    if (c.fast) {
        // Steady state: zero bounds checks (host guarantees in-bounds).
        // Offsets u*TPB are compile-time constants -> fold into LDG imm.
        for (int s = 0; s < full_sweeps; s++, i += stride) {
            float4 xv[UNROLL], iv[UNROLL];
            #pragma unroll
            for (int u = 0; u < UNROLL; u++) {
                xv[u] = __ldcs(&x[i + u * TPB]);
                iv[u] = __ldcs(&idn[i + u * TPB]);
            }
            #pragma unroll
            for (int u = 0; u < UNROLL; u++) {
                __stcs(&out[i + u * TPB], quant4_fast(xv[u], iv[u], c));
            }
        }
        // Epilogue: bounds-checked (empty when stride divides n4)
        for (; i < n4; i += stride) {
            #pragma unroll
            for (int u = 0; u < UNROLL; u++) {
                int idx = i + u * TPB;
                if (idx < n4) {
                    float4 xv = __ldcs(&x[idx]);
                    float4 iv = __ldcs(&idn[idx]);
                    __stcs(&out[idx], quant4_fast(xv, iv, c));
                }
            }
        }
    } else {
        for (int s = 0; s < full_sweeps; s++, i += stride) {
            float4 xv[UNROLL], iv[UNROLL];
            #pragma unroll
            for (int u = 0; u < UNROLL; u++) {
                xv[u] = __ldcs(&x[i + u * TPB]);
                iv[u] = __ldcs(&idn[i + u * TPB]);
            }
            #pragma unroll
            for (int u = 0; u < UNROLL; u++) {
                __stcs(&out[i + u * TPB], quant4_gen(xv[u], iv[u], c));
            }
        }
        for (; i < n4; i += stride) {
            #pragma unroll
            for (int u = 0; u < UNROLL; u++) {
                int idx = i + u * TPB;
                if (idx < n4) {
                    float4 xv = __ldcs(&x[idx]);
                    float4 iv = __ldcs(&idn[idx]);
                    __stcs(&out[idx], quant4_gen(xv, iv, c));
                }
            }
        }
    }

    // Block 0: scalar remainder (n % 4) and any extra output elements
    // (the reference also returns `scale`).
    if (blockIdx.x == 0) {
        int rem_start = n4 << 2;
        const float* xs = (const float*)x;
        const float* is = (const float*)idn;
        float*       os = (float*)out;
        for (int j = rem_start + threadIdx.x; j < n; j += TPB) {
            os[j] = quant_gen(xs[j], is[j], c);
        }
        for (int j = n + threadIdx.x; j < out_size; j += TPB) {
            os[j] = c.scale;
        }
    }
}

extern "C" void kernel_launch(void* const* d_in, const int* in_sizes, int n_in,
                              void* d_out, int out_size) {
    const float* x      = (const float*)d_in[0];
    const float* idn    = (const float*)d_in[1];
    const float* pre_sf = (const float*)d_in[2];
    const float* id_sf  = (const float*)d_in[3];
    const float* x_min  = (const float*)d_in[4];
    const float* x_max  = (const float*)d_in[5];
    float* out = (float*)d_out;

    int n  = in_sizes[0];
    int n4 = n >> 2;

    // Power-of-two grid cap so stride divides power-of-two n4 exactly
    // (n4 = 2^23 for this shape -> zero predicated work in steady state,
    //  full_sweeps = 4, every block does identical work).
    long long needed = ((long long)n4 + TPB * UNROLL - 1) / (TPB * UNROLL);
    int blocks = 2048;
    while (blocks > 1 && blocks > needed) blocks >>= 1;

    long long stride = (long long)blocks * TPB * UNROLL;
    int full_sweeps = (int)(n4 / stride);   // sweeps guaranteed fully in-bounds

    fused_quant_kernel<<<blocks, TPB>>>(
        (const float4*)x, (const float4*)idn, (float4*)out,
        pre_sf, id_sf, x_min, x_max, n4, n, out_size, full_sweeps);
}

// round 17
// speedup vs baseline: 1.0204x; 1.0204x over previous
#include <cuda_runtime.h>

#define ACC 23
#define UNROLL 4
#define TPB 256

struct Consts {
    int       nm_x, nm_id;
    int       sr_x, sr_id;
    int       sl_x, sl_id;
    int       left_x, left_id;
    int       kx32, kid32;   // (1 << (sr-1)), 0 if sr==0 (fits int32 when sr<=31)
    long long kx, kid;       // 64-bit versions for generic path
    int       fast;          // both streams eligible for 32-bit fast path
    float     scale;
};

// Exact replication of the reference's fp64 scale decomposition.
__device__ __forceinline__ void compute_consts(const float* __restrict__ pre_sf,
                                               const float* __restrict__ id_sf,
                                               const float* __restrict__ x_min,
                                               const float* __restrict__ x_max,
                                               Consts* c) {
    float scale = fmaxf(fabsf(x_min[0]), fabsf(x_max[0]));
    scale = fmaxf(scale, 1e-8f);
    scale = scale / 127.0f;
    double s64 = (double)scale;
    {
        double ns = (double)pre_sf[0] / s64;
        int e; double m = frexp(ns, &e);             // m in [0.5, 1)
        c->nm_x   = (int)llrint(m * 8388608.0);      // round-half-even == jnp.round
        c->sl_x   = max(e - ACC, 0);
        c->sr_x   = max(ACC - e, 0);
        c->left_x = (e - ACC) >= 0;
        c->kx32   = (c->sr_x > 0 && c->sr_x <= 31) ? (1 << (c->sr_x - 1)) : 0;
        c->kx     = (c->sr_x > 0) ? (1LL << (c->sr_x - 1)) : 0LL;
    }
    {
        double ns = (double)id_sf[0] / s64;
        int e; double m = frexp(ns, &e);
        c->nm_id   = (int)llrint(m * 8388608.0);
        c->sl_id   = max(e - ACC, 0);
        c->sr_id   = max(ACC - e, 0);
        c->left_id = (e - ACC) >= 0;
        c->kid32   = (c->sr_id > 0 && c->sr_id <= 31) ? (1 << (c->sr_id - 1)) : 0;
        c->kid     = (c->sr_id > 0) ? (1LL << (c->sr_id - 1)) : 0LL;
    }
    // Fast path: right-shift branch on both streams, sr in [15,31].
    // sr >= 15 guarantees |(xi*nm)>>sr| < 2^31 for |xi| < 2^22 (exact-int fp32
    // inputs from int32 accumulators), so 32-bit extraction is exact.
    c->fast = (!c->left_x && !c->left_id &&
               c->sr_x >= 15 && c->sr_x <= 31 &&
               c->sr_id >= 15 && c->sr_id <= 31);
    c->scale = scale;
}

// ---------------- generic bit-exact path (any consts) ----------------
__device__ __forceinline__ long long fpmul_gen(int xi, int nm, int sr, int sl,
                                               int left, long long k) {
    long long tmp = (long long)xi * (long long)nm;
    if (left) return tmp << sl;
    if (sr == 0) return tmp;
    return (tmp + (k - (long long)(tmp < 0))) >> sr;
}

__device__ __forceinline__ float quant_gen(float xv, float iv, const Consts& c) {
    int xi = (int)xv;
    int ii = (int)iv;
    long long rx = fpmul_gen(xi, c.nm_x,  c.sr_x,  c.sl_x,  c.left_x,  c.kx);
    long long ri = fpmul_gen(ii, c.nm_id, c.sr_id, c.sl_id, c.left_id, c.kid);
    long long s  = rx + ri;
    int q = (int)(s < -128 ? -128 : (s > 127 ? 127 : s));
    return (float)q * c.scale;
}

// ---------------- fast 32-bit path ----------------
// float -> int, exact for integer-valued v with |v| < 2^22
__device__ __forceinline__ int f2i_magic(float v) {
    float f = v + 12582912.0f;             // 2^23 + 2^22
    return __float_as_int(f) - 0x4B400000;
}
// int -> float, exact for q in [-2^22, 2^22)
__device__ __forceinline__ float i2f_magic(int q) {
    return __int_as_float(q + 0x4B400000) - 12582912.0f;
}

// round((xi*nm) / 2^sr) half-away-from-zero; nm > 0 so sign(tmp) == sign(xi).
__device__ __forceinline__ int fpmul_fast(int xi, int nm, int sr, int k) {
    unsigned b = (unsigned)xi >> 31;                       // 1 = negative
    long long tmp = (long long)xi * (long long)nm
                  + (long long)(unsigned)(k - (int)b);     // IMAD.WIDE w/ addend
    unsigned lo = (unsigned)tmp;
    unsigned hi = (unsigned)((unsigned long long)tmp >> 32);
    return (int)__funnelshift_r(lo, hi, sr);               // low 32 bits of >> sr
}

__device__ __forceinline__ float quant_fast(float xv, float iv, const Consts& c) {
    int xi = f2i_magic(xv);
    int ii = f2i_magic(iv);
    int rx = fpmul_fast(xi, c.nm_x,  c.sr_x,  c.kx32);
    int ri = fpmul_fast(ii, c.nm_id, c.sr_id, c.kid32);
    int s  = rx + ri;
    s = max(s, -128);
    s = min(s, 127);
    return i2f_magic(s) * c.scale;
}

__device__ __forceinline__ float4 quant4_fast(float4 xv, float4 iv, const Consts& c) {
    float4 ov;
    ov.x = quant_fast(xv.x, iv.x, c);
    ov.y = quant_fast(xv.y, iv.y, c);
    ov.z = quant_fast(xv.z, iv.z, c);
    ov.w = quant_fast(xv.w, iv.w, c);
    return ov;
}

__device__ __forceinline__ float4 quant4_gen(float4 xv, float4 iv, const Consts& c) {
    float4 ov;
    ov.x = quant_gen(xv.x, iv.x, c);
    ov.y = quant_gen(xv.y, iv.y, c);
    ov.z = quant_gen(xv.z, iv.z, c);
    ov.w = quant_gen(xv.w, iv.w, c);
    return ov;
}

__global__ void __launch_bounds__(TPB)
fused_quant_kernel(const float4* __restrict__ x,
                   const float4* __restrict__ idn,
                   float4* __restrict__ out,
                   const float* __restrict__ pre_sf,
                   const float* __restrict__ id_sf,
                   const float* __restrict__ x_min,
                   const float* __restrict__ x_max,
                   int n4, int n, int out_size) {
    __shared__ Consts sc;
    if (threadIdx.x == 0) {
        compute_consts(pre_sf, id_sf, x_min, x_max, &sc);
    }
    __syncthreads();
    const Consts c = sc;

    const int tile   = TPB * UNROLL;                 // float4 per block per sweep
    const int stride = gridDim.x * tile;

    if (c.fast) {
        for (int base = blockIdx.x * tile; base < n4; base += stride) {
            int i = base + threadIdx.x;
            if (base + tile <= n4) {
                // Block-uniform full tile: zero predication, imm-offset loads.
                float4 xv[UNROLL], iv[UNROLL];
                #pragma unroll
                for (int u = 0; u < UNROLL; u++) {
                    xv[u] = __ldcs(&x[i + u * TPB]);
                    iv[u] = __ldcs(&idn[i + u * TPB]);
                }
                #pragma unroll
                for (int u = 0; u < UNROLL; u++) {
                    __stcs(&out[i + u * TPB], quant4_fast(xv[u], iv[u], c));
                }
            } else {
                #pragma unroll
                for (int u = 0; u < UNROLL; u++) {
                    int idx = i + u * TPB;
                    if (idx < n4) {
                        float4 xv = __ldcs(&x[idx]);
                        float4 iv = __ldcs(&idn[idx]);
                        __stcs(&out[idx], quant4_fast(xv, iv, c));
                    }
                }
            }
        }
    } else {
        for (int base = blockIdx.x * tile; base < n4; base += stride) {
            int i = base + threadIdx.x;
            if (base + tile <= n4) {
                float4 xv[UNROLL], iv[UNROLL];
                #pragma unroll
                for (int u = 0; u < UNROLL; u++) {
                    xv[u] = __ldcs(&x[i + u * TPB]);
                    iv[u] = __ldcs(&idn[i + u * TPB]);
                }
                #pragma unroll
                for (int u = 0; u < UNROLL; u++) {
                    __stcs(&out[i + u * TPB], quant4_gen(xv[u], iv[u], c));
                }
            } else {
                #pragma unroll
                for (int u = 0; u < UNROLL; u++) {
                    int idx = i + u * TPB;
                    if (idx < n4) {
                        float4 xv = __ldcs(&x[idx]);
                        float4 iv = __ldcs(&idn[idx]);
                        __stcs(&out[idx], quant4_gen(xv, iv, c));
                    }
                }
            }
        }
    }

    // Block 0: scalar remainder (n % 4) and any extra output elements
    // (the reference also returns `scale`).
    if (blockIdx.x == 0) {
        int rem_start = n4 << 2;
        const float* xs = (const float*)x;
        const float* is = (const float*)idn;
        float*       os = (float*)out;
        for (int j = rem_start + threadIdx.x; j < n; j += TPB) {
            os[j] = quant_gen(xs[j], is[j], c);
        }
        for (int j = n + threadIdx.x; j < out_size; j += TPB) {
            os[j] = c.scale;
        }
    }
}

extern "C" void kernel_launch(void* const* d_in, const int* in_sizes, int n_in,
                              void* d_out, int out_size) {
    const float* x      = (const float*)d_in[0];
    const float* idn    = (const float*)d_in[1];
    const float* pre_sf = (const float*)d_in[2];
    const float* id_sf  = (const float*)d_in[3];
    const float* x_min  = (const float*)d_in[4];
    const float* x_max  = (const float*)d_in[5];
    float* out = (float*)d_out;

    int n  = in_sizes[0];
    int n4 = n >> 2;

    // Grid cap 2368 = 16 x 148 SMs: exact per-SM block balance (measured best).
    long long needed = ((long long)n4 + TPB * UNROLL - 1) / (TPB * UNROLL);
    int blocks = (int)(needed < 1 ? 1 : (needed > 2368 ? 2368 : needed));

    fused_quant_kernel<<<blocks, TPB>>>(
        (const float4*)x, (const float4*)idn, (float4*)out,
        pre_sf, id_sf, x_min, x_max, n4, n, out_size);
}